// round 16
// baseline (speedup 1.0000x reference)
#include <cuda_runtime.h>
#include <cuda_bf16.h>
#include <math.h>
#include <stdint.h>

#define B_    256
#define D_    1024
#define N_    65536
#define C_    8192
#define TEMP_ 0.05f
#define TOPP_ 0.1f
#define EPS_  1e-6f

#define AGG_BLOCKS 888   // 148 SMs x 6 resident blocks (regs=40, 256 thr)

// -------- scratch (device globals: no allocation allowed) --------
__device__ __nv_bfloat16 g_A2[(size_t)B_ * 1024];   // [b][k]: bf16(inputs)  (0.5 MB)
__device__ __nv_bfloat16 g_B2[(size_t)C_ * 1024];   // [c][k]: bf16(F_agg)   (16 MB)
__device__ int   g_counts[C_];   // zero-init at load; re-zeroed by k_scan each run
__device__ int   g_cnt2[C_];     // stable copy of counts for agg/focal
__device__ int   g_offsets[C_];
__device__ int   g_cursor[C_];
__device__ int   g_order[N_];
__device__ float g_sim[(size_t)B_ * C_];            // logits (8 MB)

__device__ __forceinline__ uint32_t smem_u32(const void* p) {
    uint32_t a;
    asm("{ .reg .u64 t; cvta.to.shared.u64 t, %1; cvt.u32.u64 %0, t; }" : "=r"(a) : "l"(p));
    return a;
}
__device__ __forceinline__ uint32_t swz128(uint32_t o) { return o ^ ((o >> 3) & 0x70u); }

// -------- L2-normalize queries -> bf16 --------
__global__ void k_norm(const float* __restrict__ res) {
    __shared__ float red[256];
    int b = blockIdx.x, t = threadIdx.x;
    const float* row = res + (size_t)b * D_;
    float s = 0.f;
    for (int i = t; i < D_; i += 256) { float v = row[i]; s += v * v; }
    red[t] = s; __syncthreads();
    for (int o = 128; o > 0; o >>= 1) { if (t < o) red[t] += red[t + o]; __syncthreads(); }
    float inv = rsqrtf(red[0]);
    for (int i = t; i < D_; i += 256)
        g_A2[(size_t)b * 1024 + i] = __float2bfloat16_rn(row[i] * inv);
}

// -------- histogram of labels --------
__global__ void k_hist(const int* __restrict__ labels) {
    int n = blockIdx.x * blockDim.x + threadIdx.x;
    if (n < N_) atomicAdd(&g_counts[labels[n]], 1);
}

// -------- exclusive scan; copies counts->g_cnt2, re-zeroes g_counts, zeroes out[0] --------
__global__ void __launch_bounds__(1024) k_scan(float* out) {
    __shared__ int wtot[32];
    int t = threadIdx.x, lane = t & 31, w = t >> 5;
    if (t == 0) out[0] = 0.f;                 // focal accumulates the mean here
    int base = t * 8;
    int v[8]; int tot = 0;
#pragma unroll
    for (int i = 0; i < 8; i++) { v[i] = g_counts[base + i]; tot += v[i]; }
    int inc = tot;
#pragma unroll
    for (int o = 1; o < 32; o <<= 1) {
        int x = __shfl_up_sync(0xFFFFFFFFu, inc, o);
        if (lane >= o) inc += x;
    }
    if (lane == 31) wtot[w] = inc;
    __syncthreads();
    if (w == 0) {
        int x = wtot[lane];
        int y = x;
#pragma unroll
        for (int o = 1; o < 32; o <<= 1) {
            int z = __shfl_up_sync(0xFFFFFFFFu, y, o);
            if (lane >= o) y += z;
        }
        wtot[lane] = y - x;   // exclusive
    }
    __syncthreads();
    int excl = wtot[w] + inc - tot;
#pragma unroll
    for (int i = 0; i < 8; i++) {
        g_offsets[base + i] = excl;
        g_cursor[base + i]  = excl;
        g_cnt2[base + i]    = v[i];
        g_counts[base + i]  = 0;     // ready for next graph replay
        excl += v[i];
    }
}

// -------- counting-sort scatter --------
__global__ void k_scatter(const int* __restrict__ labels) {
    int n = blockIdx.x * blockDim.x + threadIdx.x;
    if (n < N_) {
        int l = labels[n];
        int p = atomicAdd(&g_cursor[l], 1);
        g_order[p] = n;
    }
}

// -------- per-cluster mean/TEMP -> bf16 (persistent grid-stride blocks) --------
// 888 blocks each loop ~9 clusters: averages out Poisson(8) cluster-size imbalance
// that previously set the per-wave tail. Per-cluster arithmetic order unchanged.
__global__ void __launch_bounds__(256) k_agg(const float* __restrict__ feat) {
    __shared__ int idxs[64];
    int t = threadIdx.x;
    const float4* f4 = (const float4*)feat;
    for (int c = blockIdx.x; c < C_; c += AGG_BLOCKS) {
        int cnt = g_cnt2[c], off = g_offsets[c];
        float4 acc = make_float4(0.f, 0.f, 0.f, 0.f);
        for (int s0 = 0; s0 < cnt; s0 += 64) {
            int m = cnt - s0; if (m > 64) m = 64;
            if (t < m) idxs[t] = g_order[off + s0 + t];
            __syncthreads();
            int i = 0;
            for (; i + 8 <= m; i += 8) {            // 8 independent LDG.128 in flight
                float4 v0 = __ldg(f4 + (size_t)idxs[i]     * 256 + t);
                float4 v1 = __ldg(f4 + (size_t)idxs[i + 1] * 256 + t);
                float4 v2 = __ldg(f4 + (size_t)idxs[i + 2] * 256 + t);
                float4 v3 = __ldg(f4 + (size_t)idxs[i + 3] * 256 + t);
                float4 v4 = __ldg(f4 + (size_t)idxs[i + 4] * 256 + t);
                float4 v5 = __ldg(f4 + (size_t)idxs[i + 5] * 256 + t);
                float4 v6 = __ldg(f4 + (size_t)idxs[i + 6] * 256 + t);
                float4 v7 = __ldg(f4 + (size_t)idxs[i + 7] * 256 + t);
                acc.x += (v0.x + v1.x + v2.x + v3.x) + (v4.x + v5.x + v6.x + v7.x);
                acc.y += (v0.y + v1.y + v2.y + v3.y) + (v4.y + v5.y + v6.y + v7.y);
                acc.z += (v0.z + v1.z + v2.z + v3.z) + (v4.z + v5.z + v6.z + v7.z);
                acc.w += (v0.w + v1.w + v2.w + v3.w) + (v4.w + v5.w + v6.w + v7.w);
            }
            for (; i + 4 <= m; i += 4) {
                float4 v0 = __ldg(f4 + (size_t)idxs[i]     * 256 + t);
                float4 v1 = __ldg(f4 + (size_t)idxs[i + 1] * 256 + t);
                float4 v2 = __ldg(f4 + (size_t)idxs[i + 2] * 256 + t);
                float4 v3 = __ldg(f4 + (size_t)idxs[i + 3] * 256 + t);
                acc.x += v0.x + v1.x + v2.x + v3.x;
                acc.y += v0.y + v1.y + v2.y + v3.y;
                acc.z += v0.z + v1.z + v2.z + v3.z;
                acc.w += v0.w + v1.w + v2.w + v3.w;
            }
            for (; i < m; i++) {
                float4 v = __ldg(f4 + (size_t)idxs[i] * 256 + t);
                acc.x += v.x; acc.y += v.y; acc.z += v.z; acc.w += v.w;
            }
            __syncthreads();
        }
        float sc = (cnt > 0) ? 1.0f / (TEMP_ * (float)cnt) : 0.f;
        __nv_bfloat162 hA; hA.x = __float2bfloat16_rn(acc.x * sc); hA.y = __float2bfloat16_rn(acc.y * sc);
        __nv_bfloat162 hB; hB.x = __float2bfloat16_rn(acc.z * sc); hB.y = __float2bfloat16_rn(acc.w * sc);
        __nv_bfloat16* rowp = g_B2 + (size_t)c * 1024;
        *(__nv_bfloat162*)(rowp + 4 * t)     = hA;
        *(__nv_bfloat162*)(rowp + 4 * t + 2) = hB;
    }
}

// -------- GEMM: sim = bf16(A) @ bf16(B)^T via mma.sync, single pass (K=1024) --------
__global__ void __launch_bounds__(256, 1) k_gemm_mma() {
    __shared__ __align__(1024) __nv_bfloat16 shA[2][128 * 64];  // 2 x 16 KB
    __shared__ __align__(1024) __nv_bfloat16 shB[2][128 * 64];  // 2 x 16 KB
    uint32_t sA0 = smem_u32(shA[0]), sB0 = smem_u32(shB[0]);
    int tid = threadIdx.x, wid = tid >> 5, l = tid & 31;
    int nt = blockIdx.x & 63, mt = blockIdx.x >> 6;
    int b0 = mt * 128, c0 = nt * 128;
    int mw = wid >> 1, nw = wid & 1;            // warp grid 4x2

    float acc[2][8][4];
#pragma unroll
    for (int mi = 0; mi < 2; mi++)
#pragma unroll
        for (int ni = 0; ni < 8; ni++)
#pragma unroll
            for (int r = 0; r < 4; r++) acc[mi][ni][r] = 0.f;

    int ur = tid >> 3, usg = tid & 7;
    uint32_t so[4];
#pragma unroll
    for (int i = 0; i < 4; i++) so[i] = swz128((uint32_t)((ur + i * 32) * 128 + usg * 16));

    uint4 pa[4], pb[4];
    {   // preload + store chunk 0 into buffer 0
        const uint4* gA = (const uint4*)(g_A2 + (size_t)b0 * 1024);
        const uint4* gB = (const uint4*)(g_B2 + (size_t)c0 * 1024);
#pragma unroll
        for (int i = 0; i < 4; i++) {
            pa[i] = gA[(size_t)(ur + i * 32) * 128 + usg];
            pb[i] = gB[(size_t)(ur + i * 32) * 128 + usg];
        }
#pragma unroll
        for (int i = 0; i < 4; i++) {
            asm volatile("st.shared.v4.b32 [%0], {%1, %2, %3, %4};"
                         :: "r"(sA0 + so[i]), "r"(pa[i].x), "r"(pa[i].y), "r"(pa[i].z), "r"(pa[i].w) : "memory");
            asm volatile("st.shared.v4.b32 [%0], {%1, %2, %3, %4};"
                         :: "r"(sB0 + so[i]), "r"(pb[i].x), "r"(pb[i].y), "r"(pb[i].z), "r"(pb[i].w) : "memory");
        }
    }

    for (int vc = 0; vc < 16; vc++) {
        __syncthreads();
        int s = vc & 1;
        uint32_t sAc = sA0 + s * 16384, sBc = sB0 + s * 16384;

        if (vc < 15) {   // issue LDG for chunk vc+1 (hidden behind MMA below)
            int v2 = vc + 1;
            const uint4* gA = (const uint4*)(g_A2 + (size_t)b0 * 1024 + v2 * 64);
            const uint4* gB = (const uint4*)(g_B2 + (size_t)c0 * 1024 + v2 * 64);
#pragma unroll
            for (int i = 0; i < 4; i++) {
                pa[i] = gA[(size_t)(ur + i * 32) * 128 + usg];
                pb[i] = gB[(size_t)(ur + i * 32) * 128 + usg];
            }
        }

#pragma unroll
        for (int kk = 0; kk < 4; kk++) {
            uint32_t a[2][4];
#pragma unroll
            for (int mi = 0; mi < 2; mi++) {
                uint32_t row = mw * 32 + mi * 16 + (l & 15);
                uint32_t addr = sAc + swz128(row * 128 + kk * 32 + ((l >> 4) & 1) * 16);
                asm volatile("ldmatrix.sync.aligned.m8n8.x4.shared.b16 {%0,%1,%2,%3}, [%4];"
                             : "=r"(a[mi][0]), "=r"(a[mi][1]), "=r"(a[mi][2]), "=r"(a[mi][3])
                             : "r"(addr));
            }
            uint32_t bfr[8][2];
#pragma unroll
            for (int ni = 0; ni < 8; ni++) {
                uint32_t row = nw * 64 + ni * 8 + (l & 7);
                uint32_t addr = sBc + swz128(row * 128 + kk * 32 + ((l >> 3) & 1) * 16);
                asm volatile("ldmatrix.sync.aligned.m8n8.x2.shared.b16 {%0,%1}, [%2];"
                             : "=r"(bfr[ni][0]), "=r"(bfr[ni][1]) : "r"(addr));
            }
#pragma unroll
            for (int mi = 0; mi < 2; mi++)
#pragma unroll
                for (int ni = 0; ni < 8; ni++)
                    asm volatile(
                        "mma.sync.aligned.m16n8k16.row.col.f32.bf16.bf16.f32 "
                        "{%0,%1,%2,%3}, {%4,%5,%6,%7}, {%8,%9}, {%0,%1,%2,%3};"
                        : "+f"(acc[mi][ni][0]), "+f"(acc[mi][ni][1]),
                          "+f"(acc[mi][ni][2]), "+f"(acc[mi][ni][3])
                        : "r"(a[mi][0]), "r"(a[mi][1]), "r"(a[mi][2]), "r"(a[mi][3]),
                          "r"(bfr[ni][0]), "r"(bfr[ni][1]));
        }

        if (vc < 15) {   // store chunk vc+1 into the other buffer
            uint32_t dA = sA0 + (s ^ 1) * 16384, dB = sB0 + (s ^ 1) * 16384;
#pragma unroll
            for (int i = 0; i < 4; i++) {
                asm volatile("st.shared.v4.b32 [%0], {%1, %2, %3, %4};"
                             :: "r"(dA + so[i]), "r"(pa[i].x), "r"(pa[i].y), "r"(pa[i].z), "r"(pa[i].w) : "memory");
                asm volatile("st.shared.v4.b32 [%0], {%1, %2, %3, %4};"
                             :: "r"(dB + so[i]), "r"(pb[i].x), "r"(pb[i].y), "r"(pb[i].z), "r"(pb[i].w) : "memory");
            }
        }
    }

    int gr = l >> 2, gc = (l & 3) * 2;
#pragma unroll
    for (int mi = 0; mi < 2; mi++) {
        int row = b0 + mw * 32 + mi * 16 + gr;
#pragma unroll
        for (int ni = 0; ni < 8; ni++) {
            int col = c0 + nw * 64 + ni * 8 + gc;
            float2 v0; v0.x = acc[mi][ni][0]; v0.y = acc[mi][ni][1];
            float2 v1; v1.x = acc[mi][ni][2]; v1.y = acc[mi][ni][3];
            *(float2*)&g_sim[(size_t)row * C_ + col]       = v0;
            *(float2*)&g_sim[(size_t)(row + 8) * C_ + col] = v1;
        }
    }
}

// -------- focal masked softmax: radix-select; level-3 histogram fused with exp pass;
//          loss mean accumulated directly into out[0] --------
__global__ void __launch_bounds__(256) k_focal(const int* __restrict__ labels,
                                               const int* __restrict__ indexes,
                                               float* __restrict__ out) {
    __shared__ unsigned se[C_];       // float bits of masked exps (target zeroed) (32 KB)
    __shared__ float binP[8][256];    // per-warp private histograms (8 KB)
    __shared__ float wsum[8];
    __shared__ float red8[8];
    __shared__ unsigned redp[8];
    __shared__ int sh_cand, sh_nz;
    __shared__ float sh_et, sh_gA;
    __shared__ unsigned sh_pref;
    int b = blockIdx.x, t = threadIdx.x;
    int lane = t & 31, w = t >> 5;
    int tgt = labels[indexes[b]];

    // zero bins + selection scalars BEFORE the fused exp/histogram pass
#pragma unroll
    for (int j = 0; j < 8; j++) ((float*)binP)[t + j * 256] = 0.f;
    if (t == 0) { sh_cand = -1; sh_nz = 1 << 30; }
    __syncthreads();

    // exp pass + block sum + level-3 (MSB byte) histogram (prefix empty -> match==e>0)
    float ls = 0.f;
#pragma unroll
    for (int i = 0; i < 32; i++) {
        int c = t + i * 256;
        float e = 0.f;
        if (g_cnt2[c] > 0) e = __expf(g_sim[(size_t)b * C_ + c]);
        if (c == tgt) { sh_et = e; e = 0.f; }
        unsigned k = __float_as_uint(e);
        se[c] = k; ls += e;
        if (e > 0.f) atomicAdd(&binP[w][k >> 24], e);
    }
#pragma unroll
    for (int o = 16; o > 0; o >>= 1) ls += __shfl_down_sync(0xFFFFFFFFu, ls, o);
    if (lane == 0) red8[w] = ls;
    __syncthreads();
    float S = red8[0] + red8[1] + red8[2] + red8[3] + red8[4] + red8[5] + red8[6] + red8[7];
    float target = TOPP_ * S;

    unsigned pref = 0; float gAb = 0.f;
    for (int lvl = 3; lvl >= 0; lvl--) {
        int sh = lvl * 8;
        if (lvl < 3) {
            // zero bins + scalars, rebuild histogram for this level
#pragma unroll
            for (int j = 0; j < 8; j++) ((float*)binP)[t + j * 256] = 0.f;
            if (t == 0) { sh_cand = -1; sh_nz = 1 << 30; }
            __syncthreads();
#pragma unroll
            for (int i = 0; i < 32; i++) {
                unsigned k = se[t + i * 256];
                if (k != 0u && (k >> (sh + 8)) == (pref >> (sh + 8)))
                    atomicAdd(&binP[w][(k >> sh) & 0xFFu], __uint_as_float(k));
            }
            __syncthreads();
        }
        // thread t owns bin t: merge copies
        float m = 0.f;
#pragma unroll
        for (int j = 0; j < 8; j++) m += binP[j][t];
        // in-warp suffix sum (x = sum over lanes >= lane)
        float x = m;
#pragma unroll
        for (int o = 1; o < 32; o <<= 1) {
            float y = __shfl_down_sync(0xFFFFFFFFu, x, o);
            if (lane + o < 32) x += y;
        }
        if (lane == 0) wsum[w] = x;     // warp total
        __syncthreads();
        float hi = 0.f;
        for (int w2 = w + 1; w2 < 8; w2++) hi += wsum[w2];
        float suf = x + hi;             // sum of bins >= t
        // eligibility -> smem atomics
        if (m > 0.f) {
            atomicMin(&sh_nz, t);
            if (gAb + suf >= target) atomicMax(&sh_cand, t);
        }
        __syncthreads();
        int sel; bool none = false;
        if (sh_cand >= 0)            sel = sh_cand;
        else if (sh_nz < (1 << 30))  sel = sh_nz;
        else                        { sel = 0; none = true; }
        if (!none) {
            if (t == sel) { sh_pref = pref | ((unsigned)sel << sh); sh_gA = gAb + suf - m; }
        } else if (t == 0) { sh_pref = pref; sh_gA = gAb; }
        __syncthreads();
        pref = sh_pref; gAb = sh_gA;
    }

    float v = __uint_as_float(pref);
    float i0f = ceilf((target - gAb) / v);
    float thr;
    if (i0f >= 2.0f || gAb <= 0.f) {
        thr = v;
    } else {
        // predecessor: min element strictly above v (uint order == float order, all >= 0)
        unsigned pk = 0xFFFFFFFFu;
#pragma unroll
        for (int i = 0; i < 32; i++) {
            unsigned k = se[t + i * 256];
            if (k > pref && k < pk) pk = k;
        }
#pragma unroll
        for (int o = 16; o > 0; o >>= 1) {
            unsigned q = __shfl_down_sync(0xFFFFFFFFu, pk, o);
            if (q < pk) pk = q;
        }
        if (lane == 0) redp[w] = pk;
        __syncthreads();
        unsigned pm = redp[0];
#pragma unroll
        for (int j = 1; j < 8; j++) { unsigned q = redp[j]; if (q < pm) pm = q; }
        float pred = (pm == 0xFFFFFFFFu) ? v : __uint_as_float(pm);
        float d1 = target - gAb;
        float d2 = gAb + v - target;
        thr = (d1 <= d2) ? pred : v;
        __syncthreads();
    }

    // kept negatives sum
    float ks = 0.f;
#pragma unroll
    for (int i = 0; i < 32; i++) {
        float e = __uint_as_float(se[t + i * 256]);
        if (e >= thr) ks += e;
    }
#pragma unroll
    for (int o = 16; o > 0; o >>= 1) ks += __shfl_down_sync(0xFFFFFFFFu, ks, o);
    if (lane == 0) red8[w] = ks;
    __syncthreads();
    if (t == 0) {
        float kst = red8[0] + red8[1] + red8[2] + red8[3] + red8[4] + red8[5] + red8[6] + red8[7];
        float et = sh_et;
        float denom = et + kst + EPS_;
        float p = et / denom;
        atomicAdd(out, -logf(p + EPS_) * (1.0f / (float)B_));
    }
}

extern "C" void kernel_launch(void* const* d_in, const int* in_sizes, int n_in,
                              void* d_out, int out_size) {
    (void)in_sizes; (void)n_in; (void)out_size;
    const float* results  = (const float*)d_in[0];
    const float* features = (const float*)d_in[1];
    const int*   indexes  = (const int*)d_in[2];
    const int*   labels   = (const int*)d_in[3];
    float* out = (float*)d_out;

    k_hist    <<<N_ / 256, 256>>>(labels);
    k_scan    <<<1, 1024>>>(out);            // counts->g_cnt2, re-zero counts, out[0]=0
    k_scatter <<<N_ / 256, 256>>>(labels);
    k_agg     <<<AGG_BLOCKS, 256>>>(features);
    k_norm    <<<B_, 256>>>(results);
    k_gemm_mma<<<128, 256>>>();
    k_focal   <<<B_, 256>>>(labels, indexes, out);
}

// round 17
// speedup vs baseline: 1.1298x; 1.1298x over previous
#include <cuda_runtime.h>
#include <cuda_bf16.h>
#include <math.h>
#include <stdint.h>

#define B_    256
#define D_    1024
#define N_    65536
#define C_    8192
#define TEMP_ 0.05f
#define TOPP_ 0.1f
#define EPS_  1e-6f

// -------- scratch (device globals: no allocation allowed) --------
__device__ __nv_bfloat16 g_A2[(size_t)B_ * 1024];   // [b][k]: bf16(inputs)  (0.5 MB)
__device__ __nv_bfloat16 g_B2[(size_t)C_ * 1024];   // [c][k]: bf16(F_agg)   (16 MB)
__device__ int   g_counts[C_];   // zero-init at load; re-zeroed by k_scan each run
__device__ int   g_cnt2[C_];     // stable copy of counts for agg/focal
__device__ int   g_offsets[C_];
__device__ int   g_cursor[C_];
__device__ int   g_order[N_];
__device__ float g_sim[(size_t)B_ * C_];            // logits (8 MB)

__device__ __forceinline__ uint32_t smem_u32(const void* p) {
    uint32_t a;
    asm("{ .reg .u64 t; cvta.to.shared.u64 t, %1; cvt.u32.u64 %0, t; }" : "=r"(a) : "l"(p));
    return a;
}
__device__ __forceinline__ uint32_t swz128(uint32_t o) { return o ^ ((o >> 3) & 0x70u); }

// -------- histogram of labels --------
__global__ void k_hist(const int* __restrict__ labels) {
    int n = blockIdx.x * blockDim.x + threadIdx.x;
    if (n < N_) atomicAdd(&g_counts[labels[n]], 1);
}

// -------- fused: block 0 = exclusive scan of counts (+copy, re-zero, out[0]=0);
//          blocks 1..256 = L2-normalize query row (b-1) -> bf16 --------
__global__ void __launch_bounds__(1024) k_scan_norm(const float* __restrict__ res,
                                                    float* __restrict__ out) {
    int t = threadIdx.x, lane = t & 31, w = t >> 5;
    if (blockIdx.x == 0) {
        __shared__ int wtot[32];
        if (t == 0) out[0] = 0.f;                 // focal accumulates the mean here
        int base = t * 8;
        int v[8]; int tot = 0;
#pragma unroll
        for (int i = 0; i < 8; i++) { v[i] = g_counts[base + i]; tot += v[i]; }
        int inc = tot;
#pragma unroll
        for (int o = 1; o < 32; o <<= 1) {
            int x = __shfl_up_sync(0xFFFFFFFFu, inc, o);
            if (lane >= o) inc += x;
        }
        if (lane == 31) wtot[w] = inc;
        __syncthreads();
        if (w == 0) {
            int x = wtot[lane];
            int y = x;
#pragma unroll
            for (int o = 1; o < 32; o <<= 1) {
                int z = __shfl_up_sync(0xFFFFFFFFu, y, o);
                if (lane >= o) y += z;
            }
            wtot[lane] = y - x;   // exclusive
        }
        __syncthreads();
        int excl = wtot[w] + inc - tot;
#pragma unroll
        for (int i = 0; i < 8; i++) {
            g_offsets[base + i] = excl;
            g_cursor[base + i]  = excl;
            g_cnt2[base + i]    = v[i];
            g_counts[base + i]  = 0;     // ready for next graph replay
            excl += v[i];
        }
    } else {
        __shared__ float red[32];
        __shared__ float sh_inv;
        int b = blockIdx.x - 1;
        float v = res[(size_t)b * D_ + t];
        float s = v * v;
#pragma unroll
        for (int o = 16; o > 0; o >>= 1) s += __shfl_down_sync(0xFFFFFFFFu, s, o);
        if (lane == 0) red[w] = s;
        __syncthreads();
        if (w == 0) {
            float x = red[lane];
#pragma unroll
            for (int o = 16; o > 0; o >>= 1) x += __shfl_down_sync(0xFFFFFFFFu, x, o);
            if (lane == 0) sh_inv = rsqrtf(x);
        }
        __syncthreads();
        g_A2[(size_t)b * D_ + t] = __float2bfloat16_rn(v * sh_inv);
    }
}

// -------- counting-sort scatter --------
__global__ void k_scatter(const int* __restrict__ labels) {
    int n = blockIdx.x * blockDim.x + threadIdx.x;
    if (n < N_) {
        int l = labels[n];
        int p = atomicAdd(&g_cursor[l], 1);
        g_order[p] = n;
    }
}

// -------- per-cluster mean/TEMP -> bf16 (R15: one block per cluster, MLP-8) --------
__global__ void k_agg(const float* __restrict__ feat) {
    __shared__ int idxs[64];
    int c = blockIdx.x, t = threadIdx.x;
    int cnt = g_cnt2[c], off = g_offsets[c];
    const float4* f4 = (const float4*)feat;
    float4 acc = make_float4(0.f, 0.f, 0.f, 0.f);
    for (int s0 = 0; s0 < cnt; s0 += 64) {
        int m = cnt - s0; if (m > 64) m = 64;
        if (t < m) idxs[t] = g_order[off + s0 + t];
        __syncthreads();
        int i = 0;
        for (; i + 8 <= m; i += 8) {            // 8 independent LDG.128 in flight
            float4 v0 = __ldg(f4 + (size_t)idxs[i]     * 256 + t);
            float4 v1 = __ldg(f4 + (size_t)idxs[i + 1] * 256 + t);
            float4 v2 = __ldg(f4 + (size_t)idxs[i + 2] * 256 + t);
            float4 v3 = __ldg(f4 + (size_t)idxs[i + 3] * 256 + t);
            float4 v4 = __ldg(f4 + (size_t)idxs[i + 4] * 256 + t);
            float4 v5 = __ldg(f4 + (size_t)idxs[i + 5] * 256 + t);
            float4 v6 = __ldg(f4 + (size_t)idxs[i + 6] * 256 + t);
            float4 v7 = __ldg(f4 + (size_t)idxs[i + 7] * 256 + t);
            acc.x += (v0.x + v1.x + v2.x + v3.x) + (v4.x + v5.x + v6.x + v7.x);
            acc.y += (v0.y + v1.y + v2.y + v3.y) + (v4.y + v5.y + v6.y + v7.y);
            acc.z += (v0.z + v1.z + v2.z + v3.z) + (v4.z + v5.z + v6.z + v7.z);
            acc.w += (v0.w + v1.w + v2.w + v3.w) + (v4.w + v5.w + v6.w + v7.w);
        }
        for (; i + 4 <= m; i += 4) {
            float4 v0 = __ldg(f4 + (size_t)idxs[i]     * 256 + t);
            float4 v1 = __ldg(f4 + (size_t)idxs[i + 1] * 256 + t);
            float4 v2 = __ldg(f4 + (size_t)idxs[i + 2] * 256 + t);
            float4 v3 = __ldg(f4 + (size_t)idxs[i + 3] * 256 + t);
            acc.x += v0.x + v1.x + v2.x + v3.x;
            acc.y += v0.y + v1.y + v2.y + v3.y;
            acc.z += v0.z + v1.z + v2.z + v3.z;
            acc.w += v0.w + v1.w + v2.w + v3.w;
        }
        for (; i < m; i++) {
            float4 v = __ldg(f4 + (size_t)idxs[i] * 256 + t);
            acc.x += v.x; acc.y += v.y; acc.z += v.z; acc.w += v.w;
        }
        __syncthreads();
    }
    float sc = (cnt > 0) ? 1.0f / (TEMP_ * (float)cnt) : 0.f;
    __nv_bfloat162 hA; hA.x = __float2bfloat16_rn(acc.x * sc); hA.y = __float2bfloat16_rn(acc.y * sc);
    __nv_bfloat162 hB; hB.x = __float2bfloat16_rn(acc.z * sc); hB.y = __float2bfloat16_rn(acc.w * sc);
    __nv_bfloat16* rowp = g_B2 + (size_t)c * 1024;
    *(__nv_bfloat162*)(rowp + 4 * t)     = hA;
    *(__nv_bfloat162*)(rowp + 4 * t + 2) = hB;
}

// -------- GEMM: sim = bf16(A) @ bf16(B)^T via mma.sync, single pass (K=1024) --------
__global__ void __launch_bounds__(256, 1) k_gemm_mma() {
    __shared__ __align__(1024) __nv_bfloat16 shA[2][128 * 64];  // 2 x 16 KB
    __shared__ __align__(1024) __nv_bfloat16 shB[2][128 * 64];  // 2 x 16 KB
    uint32_t sA0 = smem_u32(shA[0]), sB0 = smem_u32(shB[0]);
    int tid = threadIdx.x, wid = tid >> 5, l = tid & 31;
    int nt = blockIdx.x & 63, mt = blockIdx.x >> 6;
    int b0 = mt * 128, c0 = nt * 128;
    int mw = wid >> 1, nw = wid & 1;            // warp grid 4x2

    float acc[2][8][4];
#pragma unroll
    for (int mi = 0; mi < 2; mi++)
#pragma unroll
        for (int ni = 0; ni < 8; ni++)
#pragma unroll
            for (int r = 0; r < 4; r++) acc[mi][ni][r] = 0.f;

    int ur = tid >> 3, usg = tid & 7;
    uint32_t so[4];
#pragma unroll
    for (int i = 0; i < 4; i++) so[i] = swz128((uint32_t)((ur + i * 32) * 128 + usg * 16));

    uint4 pa[4], pb[4];
    {   // preload + store chunk 0 into buffer 0
        const uint4* gA = (const uint4*)(g_A2 + (size_t)b0 * 1024);
        const uint4* gB = (const uint4*)(g_B2 + (size_t)c0 * 1024);
#pragma unroll
        for (int i = 0; i < 4; i++) {
            pa[i] = gA[(size_t)(ur + i * 32) * 128 + usg];
            pb[i] = gB[(size_t)(ur + i * 32) * 128 + usg];
        }
#pragma unroll
        for (int i = 0; i < 4; i++) {
            asm volatile("st.shared.v4.b32 [%0], {%1, %2, %3, %4};"
                         :: "r"(sA0 + so[i]), "r"(pa[i].x), "r"(pa[i].y), "r"(pa[i].z), "r"(pa[i].w) : "memory");
            asm volatile("st.shared.v4.b32 [%0], {%1, %2, %3, %4};"
                         :: "r"(sB0 + so[i]), "r"(pb[i].x), "r"(pb[i].y), "r"(pb[i].z), "r"(pb[i].w) : "memory");
        }
    }

    for (int vc = 0; vc < 16; vc++) {
        __syncthreads();
        int s = vc & 1;
        uint32_t sAc = sA0 + s * 16384, sBc = sB0 + s * 16384;

        if (vc < 15) {   // issue LDG for chunk vc+1 (hidden behind MMA below)
            int v2 = vc + 1;
            const uint4* gA = (const uint4*)(g_A2 + (size_t)b0 * 1024 + v2 * 64);
            const uint4* gB = (const uint4*)(g_B2 + (size_t)c0 * 1024 + v2 * 64);
#pragma unroll
            for (int i = 0; i < 4; i++) {
                pa[i] = gA[(size_t)(ur + i * 32) * 128 + usg];
                pb[i] = gB[(size_t)(ur + i * 32) * 128 + usg];
            }
        }

#pragma unroll
        for (int kk = 0; kk < 4; kk++) {
            uint32_t a[2][4];
#pragma unroll
            for (int mi = 0; mi < 2; mi++) {
                uint32_t row = mw * 32 + mi * 16 + (l & 15);
                uint32_t addr = sAc + swz128(row * 128 + kk * 32 + ((l >> 4) & 1) * 16);
                asm volatile("ldmatrix.sync.aligned.m8n8.x4.shared.b16 {%0,%1,%2,%3}, [%4];"
                             : "=r"(a[mi][0]), "=r"(a[mi][1]), "=r"(a[mi][2]), "=r"(a[mi][3])
                             : "r"(addr));
            }
            uint32_t bfr[8][2];
#pragma unroll
            for (int ni = 0; ni < 8; ni++) {
                uint32_t row = nw * 64 + ni * 8 + (l & 7);
                uint32_t addr = sBc + swz128(row * 128 + kk * 32 + ((l >> 3) & 1) * 16);
                asm volatile("ldmatrix.sync.aligned.m8n8.x2.shared.b16 {%0,%1}, [%2];"
                             : "=r"(bfr[ni][0]), "=r"(bfr[ni][1]) : "r"(addr));
            }
#pragma unroll
            for (int mi = 0; mi < 2; mi++)
#pragma unroll
                for (int ni = 0; ni < 8; ni++)
                    asm volatile(
                        "mma.sync.aligned.m16n8k16.row.col.f32.bf16.bf16.f32 "
                        "{%0,%1,%2,%3}, {%4,%5,%6,%7}, {%8,%9}, {%0,%1,%2,%3};"
                        : "+f"(acc[mi][ni][0]), "+f"(acc[mi][ni][1]),
                          "+f"(acc[mi][ni][2]), "+f"(acc[mi][ni][3])
                        : "r"(a[mi][0]), "r"(a[mi][1]), "r"(a[mi][2]), "r"(a[mi][3]),
                          "r"(bfr[ni][0]), "r"(bfr[ni][1]));
        }

        if (vc < 15) {   // store chunk vc+1 into the other buffer
            uint32_t dA = sA0 + (s ^ 1) * 16384, dB = sB0 + (s ^ 1) * 16384;
#pragma unroll
            for (int i = 0; i < 4; i++) {
                asm volatile("st.shared.v4.b32 [%0], {%1, %2, %3, %4};"
                             :: "r"(dA + so[i]), "r"(pa[i].x), "r"(pa[i].y), "r"(pa[i].z), "r"(pa[i].w) : "memory");
                asm volatile("st.shared.v4.b32 [%0], {%1, %2, %3, %4};"
                             :: "r"(dB + so[i]), "r"(pb[i].x), "r"(pb[i].y), "r"(pb[i].z), "r"(pb[i].w) : "memory");
            }
        }
    }

    int gr = l >> 2, gc = (l & 3) * 2;
#pragma unroll
    for (int mi = 0; mi < 2; mi++) {
        int row = b0 + mw * 32 + mi * 16 + gr;
#pragma unroll
        for (int ni = 0; ni < 8; ni++) {
            int col = c0 + nw * 64 + ni * 8 + gc;
            float2 v0; v0.x = acc[mi][ni][0]; v0.y = acc[mi][ni][1];
            float2 v1; v1.x = acc[mi][ni][2]; v1.y = acc[mi][ni][3];
            *(float2*)&g_sim[(size_t)row * C_ + col]       = v0;
            *(float2*)&g_sim[(size_t)(row + 8) * C_ + col] = v1;
        }
    }
}

// -------- focal masked softmax: radix-select; level-3 histogram fused with exp pass;
//          loss mean accumulated directly into out[0] --------
__global__ void __launch_bounds__(256) k_focal(const int* __restrict__ labels,
                                               const int* __restrict__ indexes,
                                               float* __restrict__ out) {
    __shared__ unsigned se[C_];       // float bits of masked exps (target zeroed) (32 KB)
    __shared__ float binP[8][256];    // per-warp private histograms (8 KB)
    __shared__ float wsum[8];
    __shared__ float red8[8];
    __shared__ unsigned redp[8];
    __shared__ int sh_cand, sh_nz;
    __shared__ float sh_et, sh_gA;
    __shared__ unsigned sh_pref;
    int b = blockIdx.x, t = threadIdx.x;
    int lane = t & 31, w = t >> 5;
    int tgt = labels[indexes[b]];

    // zero bins + selection scalars BEFORE the fused exp/histogram pass
#pragma unroll
    for (int j = 0; j < 8; j++) ((float*)binP)[t + j * 256] = 0.f;
    if (t == 0) { sh_cand = -1; sh_nz = 1 << 30; }
    __syncthreads();

    // exp pass + block sum + level-3 (MSB byte) histogram (prefix empty -> match==e>0)
    float ls = 0.f;
#pragma unroll
    for (int i = 0; i < 32; i++) {
        int c = t + i * 256;
        float e = 0.f;
        if (g_cnt2[c] > 0) e = __expf(g_sim[(size_t)b * C_ + c]);
        if (c == tgt) { sh_et = e; e = 0.f; }
        unsigned k = __float_as_uint(e);
        se[c] = k; ls += e;
        if (e > 0.f) atomicAdd(&binP[w][k >> 24], e);
    }
#pragma unroll
    for (int o = 16; o > 0; o >>= 1) ls += __shfl_down_sync(0xFFFFFFFFu, ls, o);
    if (lane == 0) red8[w] = ls;
    __syncthreads();
    float S = red8[0] + red8[1] + red8[2] + red8[3] + red8[4] + red8[5] + red8[6] + red8[7];
    float target = TOPP_ * S;

    unsigned pref = 0; float gAb = 0.f;
    for (int lvl = 3; lvl >= 0; lvl--) {
        int sh = lvl * 8;
        if (lvl < 3) {
            // zero bins + scalars, rebuild histogram for this level
#pragma unroll
            for (int j = 0; j < 8; j++) ((float*)binP)[t + j * 256] = 0.f;
            if (t == 0) { sh_cand = -1; sh_nz = 1 << 30; }
            __syncthreads();
#pragma unroll
            for (int i = 0; i < 32; i++) {
                unsigned k = se[t + i * 256];
                if (k != 0u && (k >> (sh + 8)) == (pref >> (sh + 8)))
                    atomicAdd(&binP[w][(k >> sh) & 0xFFu], __uint_as_float(k));
            }
            __syncthreads();
        }
        // thread t owns bin t: merge copies
        float m = 0.f;
#pragma unroll
        for (int j = 0; j < 8; j++) m += binP[j][t];
        // in-warp suffix sum (x = sum over lanes >= lane)
        float x = m;
#pragma unroll
        for (int o = 1; o < 32; o <<= 1) {
            float y = __shfl_down_sync(0xFFFFFFFFu, x, o);
            if (lane + o < 32) x += y;
        }
        if (lane == 0) wsum[w] = x;     // warp total
        __syncthreads();
        float hi = 0.f;
        for (int w2 = w + 1; w2 < 8; w2++) hi += wsum[w2];
        float suf = x + hi;             // sum of bins >= t
        // eligibility -> smem atomics
        if (m > 0.f) {
            atomicMin(&sh_nz, t);
            if (gAb + suf >= target) atomicMax(&sh_cand, t);
        }
        __syncthreads();
        int sel; bool none = false;
        if (sh_cand >= 0)            sel = sh_cand;
        else if (sh_nz < (1 << 30))  sel = sh_nz;
        else                        { sel = 0; none = true; }
        if (!none) {
            if (t == sel) { sh_pref = pref | ((unsigned)sel << sh); sh_gA = gAb + suf - m; }
        } else if (t == 0) { sh_pref = pref; sh_gA = gAb; }
        __syncthreads();
        pref = sh_pref; gAb = sh_gA;
    }

    float v = __uint_as_float(pref);
    float i0f = ceilf((target - gAb) / v);
    float thr;
    if (i0f >= 2.0f || gAb <= 0.f) {
        thr = v;
    } else {
        // predecessor: min element strictly above v (uint order == float order, all >= 0)
        unsigned pk = 0xFFFFFFFFu;
#pragma unroll
        for (int i = 0; i < 32; i++) {
            unsigned k = se[t + i * 256];
            if (k > pref && k < pk) pk = k;
        }
#pragma unroll
        for (int o = 16; o > 0; o >>= 1) {
            unsigned q = __shfl_down_sync(0xFFFFFFFFu, pk, o);
            if (q < pk) pk = q;
        }
        if (lane == 0) redp[w] = pk;
        __syncthreads();
        unsigned pm = redp[0];
#pragma unroll
        for (int j = 1; j < 8; j++) { unsigned q = redp[j]; if (q < pm) pm = q; }
        float pred = (pm == 0xFFFFFFFFu) ? v : __uint_as_float(pm);
        float d1 = target - gAb;
        float d2 = gAb + v - target;
        thr = (d1 <= d2) ? pred : v;
        __syncthreads();
    }

    // kept negatives sum
    float ks = 0.f;
#pragma unroll
    for (int i = 0; i < 32; i++) {
        float e = __uint_as_float(se[t + i * 256]);
        if (e >= thr) ks += e;
    }
#pragma unroll
    for (int o = 16; o > 0; o >>= 1) ks += __shfl_down_sync(0xFFFFFFFFu, ks, o);
    if (lane == 0) red8[w] = ks;
    __syncthreads();
    if (t == 0) {
        float kst = red8[0] + red8[1] + red8[2] + red8[3] + red8[4] + red8[5] + red8[6] + red8[7];
        float et = sh_et;
        float denom = et + kst + EPS_;
        float p = et / denom;
        atomicAdd(out, -logf(p + EPS_) * (1.0f / (float)B_));
    }
}

extern "C" void kernel_launch(void* const* d_in, const int* in_sizes, int n_in,
                              void* d_out, int out_size) {
    (void)in_sizes; (void)n_in; (void)out_size;
    const float* results  = (const float*)d_in[0];
    const float* features = (const float*)d_in[1];
    const int*   indexes  = (const int*)d_in[2];
    const int*   labels   = (const int*)d_in[3];
    float* out = (float*)d_out;

    k_hist     <<<N_ / 256, 256>>>(labels);
    k_scan_norm<<<1 + B_, 1024>>>(results, out);  // scan + counts copy + norm (fused)
    k_scatter  <<<N_ / 256, 256>>>(labels);
    k_agg      <<<C_, 256>>>(features);
    k_gemm_mma <<<128, 256>>>();
    k_focal    <<<B_, 256>>>(labels, indexes, out);
}